// round 1
// baseline (speedup 1.0000x reference)
#include <cuda_runtime.h>

// ---------------------------------------------------------------------------
// Static scratch (sanctioned workaround for no-alloc rule)
// ---------------------------------------------------------------------------
#define NMAX 250112  // >= 250000, multiple of 64

__device__ __align__(256) float g_X  [(size_t)NMAX * 64];
__device__ __align__(256) float g_F1 [(size_t)NMAX * 64];
__device__ __align__(256) float g_F2a[(size_t)NMAX * 32];
__device__ __align__(256) float g_F2b[(size_t)NMAX * 32];
__device__ __align__(256) float g_A8 [(size_t)NMAX * 8];
__device__ __align__(256) float g_T8 [(size_t)NMAX * 8];
__device__ int  g_cnt1[27];
__device__ int  g_cntd[8];
__device__ __align__(256) int2 g_pairs1[(size_t)27 * NMAX];
__device__ __align__(256) int2 g_pairsd[(size_t)8  * NMAX];

// ---------------------------------------------------------------------------
// Elementwise helpers
// ---------------------------------------------------------------------------
__global__ void k_add(const float4* __restrict__ a, const float4* __restrict__ b,
                      float4* __restrict__ o, int n4) {
    int t = blockIdx.x * blockDim.x + threadIdx.x;
    if (t < n4) {
        float4 x = a[t], y = b[t];
        o[t] = make_float4(x.x + y.x, x.y + y.y, x.z + y.z, x.w + y.w);
    }
}

__global__ void k_bias_init32(float* __restrict__ buf, const float* __restrict__ b, int n) {
    int t = blockIdx.x * blockDim.x + threadIdx.x;
    if (t < n) buf[t] = b[t & 31];
}

__global__ void k_relu(float* __restrict__ buf, int n) {
    int t = blockIdx.x * blockDim.x + threadIdx.x;
    if (t < n) buf[t] = fmaxf(buf[t], 0.0f);
}

// ---------------------------------------------------------------------------
// Pair-list construction (valid-neighbor compaction)
// ---------------------------------------------------------------------------
__global__ void k_zero_cnt() {
    int t = threadIdx.x;
    if (t < 27) g_cnt1[t] = 0;
    if (t < 8)  g_cntd[t] = 0;
}

__global__ void k_build1(const int* __restrict__ idx, int total) {  // total = N*27
    int t = blockIdx.x * blockDim.x + threadIdx.x;
    if (t >= total) return;
    int k = t % 27;
    if (k == 13) return;                 // center offset handled densely
    int j = idx[t];
    if (j < 0) return;
    int i = t / 27;
    int p = atomicAdd(&g_cnt1[k], 1);
    g_pairs1[(size_t)k * NMAX + p] = make_int2(i, j);
}

__global__ void k_buildd(const int* __restrict__ idx, int total) {  // total = N2*8
    int t = blockIdx.x * blockDim.x + threadIdx.x;
    if (t >= total) return;
    int k = t % 8;
    int j = idx[t];
    if (j < 0) return;
    int i = t / 8;
    int p = atomicAdd(&g_cntd[k], 1);
    g_pairsd[(size_t)k * NMAX + p] = make_int2(i, j);
}

// ---------------------------------------------------------------------------
// conv1 center offset (k==13, identity map): F1 = X @ W13 + b1  (dense GEMM)
// block = 256 threads, tile = 64 points x 64 out-channels
// ---------------------------------------------------------------------------
__global__ void k_conv1_center(const float* __restrict__ W, const float* __restrict__ b1,
                               const float* __restrict__ src, float* __restrict__ dst, int N) {
    __shared__ float xs[64][68];
    __shared__ float ws[64][68];
    int tid = threadIdx.x;
    int base = blockIdx.x * 64;

    const float4* W4 = (const float4*)(W + 13 * 4096);
    for (int f = tid; f < 1024; f += 256) {
        int c = f >> 4, oq = f & 15;
        *(float4*)&ws[c][oq * 4] = W4[f];
    }
    int r = tid & 63, cg = tid >> 6;
#pragma unroll
    for (int m = 0; m < 4; m++) {
        int cc = cg * 4 + m;
        float4 v = make_float4(0.f, 0.f, 0.f, 0.f);
        if (base + r < N) v = ((const float4*)src)[(size_t)(base + r) * 16 + cc];
        xs[cc * 4 + 0][r] = v.x; xs[cc * 4 + 1][r] = v.y;
        xs[cc * 4 + 2][r] = v.z; xs[cc * 4 + 3][r] = v.w;
    }
    __syncthreads();

    int p0 = (tid & 15) * 4, o0 = (tid >> 4) * 4;
    float acc[4][4] = {};
#pragma unroll 8
    for (int c = 0; c < 64; c++) {
        float4 a = *(float4*)&xs[c][p0];
        float4 w = *(float4*)&ws[c][o0];
        acc[0][0] += a.x * w.x; acc[0][1] += a.x * w.y; acc[0][2] += a.x * w.z; acc[0][3] += a.x * w.w;
        acc[1][0] += a.y * w.x; acc[1][1] += a.y * w.y; acc[1][2] += a.y * w.z; acc[1][3] += a.y * w.w;
        acc[2][0] += a.z * w.x; acc[2][1] += a.z * w.y; acc[2][2] += a.z * w.z; acc[2][3] += a.z * w.w;
        acc[3][0] += a.w * w.x; acc[3][1] += a.w * w.y; acc[3][2] += a.w * w.z; acc[3][3] += a.w * w.w;
    }
    float4 bb = ((const float4*)b1)[o0 >> 2];
#pragma unroll
    for (int p = 0; p < 4; p++) {
        int i = base + p0 + p;
        if (i < N) {
            float4 o = make_float4(acc[p][0] + bb.x, acc[p][1] + bb.y,
                                   acc[p][2] + bb.z, acc[p][3] + bb.w);
            ((float4*)dst)[(size_t)i * 16 + (o0 >> 2)] = o;
        }
    }
}

// ---------------------------------------------------------------------------
// Pair-compacted gather-GEMM with atomic accumulation.
// CIN = 64 fixed. Tile: 64 pairs x COUT outputs. grid = (tiles, K)
// ---------------------------------------------------------------------------
template <int COUT, bool RELU_SRC>
__global__ void k_pair_gemm(const float* __restrict__ W, const int2* __restrict__ pairsBase,
                            const int* __restrict__ cntArr, const float* __restrict__ src,
                            float* __restrict__ dst) {
    int k = blockIdx.y;
    int n = cntArr[k];
    int t0 = blockIdx.x * 64;
    if (t0 >= n) return;

    __shared__ float xs[64][68];
    __shared__ float ws[64][COUT + 4];
    __shared__ int sdst[64];
    __shared__ int ssrc[64];

    int tid = threadIdx.x;
    const float4* W4 = (const float4*)(W + (size_t)k * 64 * COUT);
    for (int f = tid; f < 64 * COUT / 4; f += 256) {
        int c = f / (COUT / 4), oq = f % (COUT / 4);
        *(float4*)&ws[c][oq * 4] = W4[f];
    }
    if (tid < 64) {
        int2 pr = make_int2(-1, -1);
        if (t0 + tid < n) pr = pairsBase[(size_t)k * NMAX + t0 + tid];
        sdst[tid] = pr.x; ssrc[tid] = pr.y;
    }
    __syncthreads();

    int r = tid & 63, cg = tid >> 6;
    int j = ssrc[r];
#pragma unroll
    for (int m = 0; m < 4; m++) {
        int cc = cg * 4 + m;
        float4 v = make_float4(0.f, 0.f, 0.f, 0.f);
        if (j >= 0) v = ((const float4*)src)[(size_t)j * 16 + cc];
        if (RELU_SRC) {
            v.x = fmaxf(v.x, 0.f); v.y = fmaxf(v.y, 0.f);
            v.z = fmaxf(v.z, 0.f); v.w = fmaxf(v.w, 0.f);
        }
        xs[cc * 4 + 0][r] = v.x; xs[cc * 4 + 1][r] = v.y;
        xs[cc * 4 + 2][r] = v.z; xs[cc * 4 + 3][r] = v.w;
    }
    __syncthreads();

    constexpr int CT = COUT / 16;
    int p0 = (tid & 15) * 4, o0 = (tid >> 4) * CT;
    float acc[4][CT] = {};
#pragma unroll 8
    for (int c = 0; c < 64; c++) {
        float4 a = *(float4*)&xs[c][p0];
#pragma unroll
        for (int q = 0; q < CT; q++) {
            float w = ws[c][o0 + q];
            acc[0][q] += a.x * w; acc[1][q] += a.y * w;
            acc[2][q] += a.z * w; acc[3][q] += a.w * w;
        }
    }
#pragma unroll
    for (int p = 0; p < 4; p++) {
        int d = sdst[p0 + p];
        if (d >= 0) {
#pragma unroll
            for (int q = 0; q < CT; q++)
                atomicAdd(&dst[(size_t)d * COUT + o0 + q], acc[p][q]);
        }
    }
}

// ---------------------------------------------------------------------------
// Dense-k 27-offset conv for small channels (idx2 lattice, ~42% density).
// Thread handles PT consecutive points; weights staged in smem (broadcast LDS).
// out[i*outStride + outOff + o] = (relu?)(conv + b) (+ res[i*32 + outOff + o])
// ---------------------------------------------------------------------------
template <int CIN, int COUT, int PT, bool RELU, bool RES>
__global__ void k_conv27(const float* __restrict__ feat, const int* __restrict__ idx,
                         const float* __restrict__ W, const float* __restrict__ b,
                         const float* __restrict__ res, float* __restrict__ out,
                         int outStride, int outOff, int N) {
    __shared__ float ws[27 * CIN * COUT];
    __shared__ float sb[COUT];
    int tid = threadIdx.x;
    for (int f = tid; f < 27 * CIN * COUT; f += blockDim.x) ws[f] = W[f];
    if (tid < COUT) sb[tid] = b[tid];
    __syncthreads();

    int i0 = (blockIdx.x * blockDim.x + tid) * PT;

    float acc[PT][COUT];
#pragma unroll
    for (int p = 0; p < PT; p++)
#pragma unroll
        for (int o = 0; o < COUT; o++) acc[p][o] = 0.0f;

    for (int k = 0; k < 27; k++) {
        int jj[PT];
#pragma unroll
        for (int p = 0; p < PT; p++) {
            int i = i0 + p;
            jj[p] = (i < N) ? idx[(size_t)i * 27 + k] : -1;
        }
        const float* wk = &ws[k * CIN * COUT];
#pragma unroll
        for (int c4 = 0; c4 < CIN / 4; c4++) {
            float vv[PT][4];
#pragma unroll
            for (int p = 0; p < PT; p++) {
                float4 v = make_float4(0.f, 0.f, 0.f, 0.f);
                if (jj[p] >= 0) v = ((const float4*)feat)[(size_t)jj[p] * (CIN / 4) + c4];
                vv[p][0] = v.x; vv[p][1] = v.y; vv[p][2] = v.z; vv[p][3] = v.w;
            }
#pragma unroll
            for (int cc = 0; cc < 4; cc++) {
#pragma unroll
                for (int o = 0; o < COUT; o++) {
                    float w = wk[(c4 * 4 + cc) * COUT + o];
#pragma unroll
                    for (int p = 0; p < PT; p++) acc[p][o] += vv[p][cc] * w;
                }
            }
        }
    }

#pragma unroll
    for (int p = 0; p < PT; p++) {
        int i = i0 + p;
        if (i < N) {
            float tmp[COUT];
#pragma unroll
            for (int o = 0; o < COUT; o++) {
                float x = acc[p][o] + sb[o];
                if (RELU) x = fmaxf(x, 0.0f);
                tmp[o] = x;
            }
            float* op = out + (size_t)i * outStride + outOff;
            const float* rp = RES ? (res + (size_t)i * 32 + outOff) : nullptr;
#pragma unroll
            for (int q = 0; q < COUT / 4; q++) {
                float4 t4 = make_float4(tmp[q * 4 + 0], tmp[q * 4 + 1],
                                        tmp[q * 4 + 2], tmp[q * 4 + 3]);
                if (RES) {
                    float4 r4 = ((const float4*)rp)[q];
                    t4.x += r4.x; t4.y += r4.y; t4.z += r4.z; t4.w += r4.w;
                }
                ((float4*)op)[q] = t4;
            }
        }
    }
}

// ---------------------------------------------------------------------------
// Pointwise (kernel-size-1) conv: out = (relu?)(feat @ W + b) (+ res)
// ---------------------------------------------------------------------------
template <int CIN, int COUT, bool RELU, bool RES>
__global__ void k_pw(const float* __restrict__ feat, const float* __restrict__ W,
                     const float* __restrict__ b, const float* __restrict__ res,
                     float* __restrict__ out, int outStride, int outOff, int N) {
    __shared__ float ws[CIN * COUT];
    __shared__ float sb[COUT];
    int tid = threadIdx.x;
    for (int f = tid; f < CIN * COUT; f += blockDim.x) ws[f] = W[f];
    if (tid < COUT) sb[tid] = b[tid];
    __syncthreads();

    int i = blockIdx.x * blockDim.x + tid;
    if (i >= N) return;

    float acc[COUT];
#pragma unroll
    for (int o = 0; o < COUT; o++) acc[o] = sb[o];

#pragma unroll
    for (int c4 = 0; c4 < CIN / 4; c4++) {
        float4 v = ((const float4*)feat)[(size_t)i * (CIN / 4) + c4];
        float vv[4] = {v.x, v.y, v.z, v.w};
#pragma unroll
        for (int cc = 0; cc < 4; cc++)
#pragma unroll
            for (int o = 0; o < COUT; o++)
                acc[o] += vv[cc] * ws[(c4 * 4 + cc) * COUT + o];
    }

    float* op = out + (size_t)i * outStride + outOff;
#pragma unroll
    for (int q = 0; q < COUT / 4; q++) {
        float4 t4 = make_float4(acc[q * 4 + 0], acc[q * 4 + 1], acc[q * 4 + 2], acc[q * 4 + 3]);
        if (RELU) {
            t4.x = fmaxf(t4.x, 0.f); t4.y = fmaxf(t4.y, 0.f);
            t4.z = fmaxf(t4.z, 0.f); t4.w = fmaxf(t4.w, 0.f);
        }
        if (RES) {
            float4 r4 = ((const float4*)(res + (size_t)i * 32 + outOff))[q];
            t4.x += r4.x; t4.y += r4.y; t4.z += r4.z; t4.w += r4.w;
        }
        ((float4*)op)[q] = t4;
    }
}

// ---------------------------------------------------------------------------
// Host launcher
// ---------------------------------------------------------------------------
extern "C" void kernel_launch(void* const* d_in, const int* in_sizes, int n_in,
                              void* d_out, int out_size) {
    const float* x_feat = (const float*)d_in[0];
    const float* f1_ref = (const float*)d_in[1];
    const float* w1     = (const float*)d_in[2];
    const float* b1     = (const float*)d_in[3];
    const float* wd     = (const float*)d_in[4];
    const float* bd     = (const float*)d_in[5];
    const float* rw00   = (const float*)d_in[6];
    const float* rb00   = (const float*)d_in[7];
    const float* rw01   = (const float*)d_in[8];
    const float* rb01   = (const float*)d_in[9];
    const float* rw10   = (const float*)d_in[10];
    const float* rb10   = (const float*)d_in[11];
    const float* rw11   = (const float*)d_in[12];
    const float* rb11   = (const float*)d_in[13];
    const float* rw12   = (const float*)d_in[14];
    const float* rb12   = (const float*)d_in[15];
    const float* w4     = (const float*)d_in[16];
    const float* b4     = (const float*)d_in[17];
    const int*   idx1   = (const int*)d_in[18];
    const int*   idxd   = (const int*)d_in[19];
    const int*   idx2   = (const int*)d_in[20];
    float* outp = (float*)d_out;

    int N  = in_sizes[0] / 64;
    int N2 = in_sizes[19] / 8;

    float *pX, *pF1, *pF2a, *pF2b, *pA8, *pT8;
    int *pCnt1, *pCntd;
    int2 *pPairs1, *pPairsd;
    cudaGetSymbolAddress((void**)&pX, g_X);
    cudaGetSymbolAddress((void**)&pF1, g_F1);
    cudaGetSymbolAddress((void**)&pF2a, g_F2a);
    cudaGetSymbolAddress((void**)&pF2b, g_F2b);
    cudaGetSymbolAddress((void**)&pA8, g_A8);
    cudaGetSymbolAddress((void**)&pT8, g_T8);
    cudaGetSymbolAddress((void**)&pCnt1, g_cnt1);
    cudaGetSymbolAddress((void**)&pCntd, g_cntd);
    cudaGetSymbolAddress((void**)&pPairs1, g_pairs1);
    cudaGetSymbolAddress((void**)&pPairsd, g_pairsd);

    // --- setup: residual add + pair compaction ---
    {
        int n4 = N * 16;
        k_add<<<(n4 + 255) / 256, 256>>>((const float4*)x_feat, (const float4*)f1_ref,
                                         (float4*)pX, n4);
    }
    k_zero_cnt<<<1, 32>>>();
    k_build1<<<(N * 27 + 255) / 256, 256>>>(idx1, N * 27);
    k_buildd<<<(N2 * 8 + 255) / 256, 256>>>(idxd, N2 * 8);

    // --- conv1: center dense + 26 compacted offset GEMMs (atomic accumulate) ---
    k_conv1_center<<<(N + 63) / 64, 256>>>(w1, b1, pX, pF1, N);
    {
        dim3 g((N + 63) / 64, 27);
        k_pair_gemm<64, false><<<g, 256>>>(w1, pPairs1, pCnt1, pX, pF1);
    }

    // --- down conv (k2/s2): init with bias, pair GEMMs over relu(F1), then relu ---
    k_bias_init32<<<(N2 * 32 + 255) / 256, 256>>>(pF2a, bd, N2 * 32);
    {
        dim3 g((N2 + 63) / 64, 8);
        k_pair_gemm<32, true><<<g, 256>>>(wd, pPairsd, pCntd, pF1, pF2a);
    }
    k_relu<<<(N2 * 32 + 255) / 256, 256>>>(pF2a, N2 * 32);

    // --- 3 InceptionResNet blocks ---
    float* F  = pF2a;
    float* Fn = pF2b;
    for (int i = 0; i < 3; i++) {
        const float* W00 = rw00 + (size_t)i * 27 * 32 * 8;
        const float* B00 = rb00 + (size_t)i * 8;
        const float* W01 = rw01 + (size_t)i * 27 * 8 * 16;
        const float* B01 = rb01 + (size_t)i * 16;
        const float* W10 = rw10 + (size_t)i * 32 * 8;
        const float* B10 = rb10 + (size_t)i * 8;
        const float* W11 = rw11 + (size_t)i * 27 * 8 * 8;
        const float* B11 = rb11 + (size_t)i * 8;
        const float* W12 = rw12 + (size_t)i * 8 * 16;
        const float* B12 = rb12 + (size_t)i * 16;

        // A8 = relu(conv27(F, rw00))          [32 -> 8]
        k_conv27<32, 8, 4, true, false><<<(N2 + 511) / 512, 128>>>(
            F, idx2, W00, B00, nullptr, pA8, 8, 0, N2);
        // Fn[:, 0:16] = conv27(A8, rw01) + F[:, 0:16]   [8 -> 16]
        k_conv27<8, 16, 2, false, true><<<(N2 + 255) / 256, 128>>>(
            pA8, idx2, W01, B01, F, Fn, 32, 0, N2);
        // T8 = relu(F @ rw10 + b)             [32 -> 8]
        k_pw<32, 8, true, false><<<(N2 + 127) / 128, 128>>>(
            F, W10, B10, nullptr, pT8, 8, 0, N2);
        // A8 = relu(conv27(T8, rw11))         [8 -> 8]
        k_conv27<8, 8, 4, true, false><<<(N2 + 511) / 512, 128>>>(
            pT8, idx2, W11, B11, nullptr, pA8, 8, 0, N2);
        // Fn[:, 16:32] = A8 @ rw12 + b + F[:, 16:32]    [8 -> 16]
        k_pw<8, 16, false, true><<<(N2 + 127) / 128, 128>>>(
            pA8, W12, B12, F, Fn, 32, 16, N2);

        float* t = F; F = Fn; Fn = t;
    }

    // --- enc4: conv27(F, w4) + b4 -> output  [32 -> 8] ---
    k_conv27<32, 8, 4, false, false><<<(N2 + 511) / 512, 128>>>(
        F, idx2, w4, b4, nullptr, outp, 8, 0, N2);
}

// round 2
// speedup vs baseline: 1.1636x; 1.1636x over previous
#include <cuda_runtime.h>

// ---------------------------------------------------------------------------
// Static scratch (sanctioned workaround for no-alloc rule)
// ---------------------------------------------------------------------------
#define NMAX 250112  // >= 250000, multiple of 64

__device__ __align__(256) float g_X  [(size_t)NMAX * 64];
__device__ __align__(256) float g_F1 [(size_t)NMAX * 64];
__device__ __align__(256) float g_F2a[(size_t)NMAX * 32];
__device__ __align__(256) float g_F2b[(size_t)NMAX * 32];
__device__ __align__(256) float g_A8 [(size_t)NMAX * 8];
__device__ __align__(256) float g_T8 [(size_t)NMAX * 8];
__device__ int  g_cnt1[27];
__device__ int  g_cntd[8];
__device__ __align__(256) int2 g_pairs1[(size_t)27 * NMAX];
__device__ __align__(256) int2 g_pairsd[(size_t)8  * NMAX];

// ---------------------------------------------------------------------------
// Vector reduction helper (sm_90+): one LTS request for 4 channels
// ---------------------------------------------------------------------------
__device__ __forceinline__ void red_add_v4(float* p, float4 v) {
    asm volatile("red.global.add.v4.f32 [%0], {%1, %2, %3, %4};"
                 :: "l"(p), "f"(v.x), "f"(v.y), "f"(v.z), "f"(v.w)
                 : "memory");
}

// ---------------------------------------------------------------------------
// Elementwise helpers
// ---------------------------------------------------------------------------
__global__ void k_add(const float4* __restrict__ a, const float4* __restrict__ b,
                      float4* __restrict__ o, int n4) {
    int t = blockIdx.x * blockDim.x + threadIdx.x;
    if (t < n4) {
        float4 x = a[t], y = b[t];
        o[t] = make_float4(x.x + y.x, x.y + y.y, x.z + y.z, x.w + y.w);
    }
}

__global__ void k_bias_init32(float* __restrict__ buf, const float* __restrict__ b, int n) {
    int t = blockIdx.x * blockDim.x + threadIdx.x;
    if (t < n) buf[t] = b[t & 31];
}

__global__ void k_relu(float* __restrict__ buf, int n) {
    int t = blockIdx.x * blockDim.x + threadIdx.x;
    if (t < n) buf[t] = fmaxf(buf[t], 0.0f);
}

// ---------------------------------------------------------------------------
// Pair-list construction with BLOCK-AGGREGATED atomics.
// Per block: smem histogram over k, one global atomic per (block, k).
// ---------------------------------------------------------------------------
__global__ void k_zero_cnt() {
    int t = threadIdx.x;
    if (t < 27) g_cnt1[t] = 0;
    if (t < 8)  g_cntd[t] = 0;
}

__global__ void k_build1(const int* __restrict__ idx, int total) {  // total = N*27
    __shared__ int scnt[27];
    __shared__ int sbase[27];
    int tid = threadIdx.x;
    if (tid < 27) scnt[tid] = 0;
    __syncthreads();

    int t = blockIdx.x * blockDim.x + tid;
    int k = -1, i = 0, j = 0, rank = 0;
    if (t < total) {
        int kk = t % 27;
        if (kk != 13) {                 // center offset handled densely
            int jj = idx[t];
            if (jj >= 0) {
                k = kk; j = jj; i = t / 27;
                rank = atomicAdd(&scnt[k], 1);
            }
        }
    }
    __syncthreads();
    if (tid < 27 && scnt[tid] > 0)
        sbase[tid] = atomicAdd(&g_cnt1[tid], scnt[tid]);
    __syncthreads();
    if (k >= 0)
        g_pairs1[(size_t)k * NMAX + sbase[k] + rank] = make_int2(i, j);
}

__global__ void k_buildd(const int* __restrict__ idx, int total) {  // total = N2*8
    __shared__ int scnt[8];
    __shared__ int sbase[8];
    int tid = threadIdx.x;
    if (tid < 8) scnt[tid] = 0;
    __syncthreads();

    int t = blockIdx.x * blockDim.x + tid;
    int k = -1, i = 0, j = 0, rank = 0;
    if (t < total) {
        int jj = idx[t];
        if (jj >= 0) {
            k = t % 8; j = jj; i = t / 8;
            rank = atomicAdd(&scnt[k], 1);
        }
    }
    __syncthreads();
    if (tid < 8 && scnt[tid] > 0)
        sbase[tid] = atomicAdd(&g_cntd[tid], scnt[tid]);
    __syncthreads();
    if (k >= 0)
        g_pairsd[(size_t)k * NMAX + sbase[k] + rank] = make_int2(i, j);
}

// ---------------------------------------------------------------------------
// conv1 center offset (k==13, identity map): F1 = X @ W13 + b1  (dense GEMM)
// block = 256 threads, tile = 64 points x 64 out-channels
// ---------------------------------------------------------------------------
__global__ void k_conv1_center(const float* __restrict__ W, const float* __restrict__ b1,
                               const float* __restrict__ src, float* __restrict__ dst, int N) {
    __shared__ float xs[64][68];
    __shared__ float ws[64][68];
    int tid = threadIdx.x;
    int base = blockIdx.x * 64;

    const float4* W4 = (const float4*)(W + 13 * 4096);
    for (int f = tid; f < 1024; f += 256) {
        int c = f >> 4, oq = f & 15;
        *(float4*)&ws[c][oq * 4] = W4[f];
    }
    int r = tid & 63, cg = tid >> 6;
#pragma unroll
    for (int m = 0; m < 4; m++) {
        int cc = cg * 4 + m;
        float4 v = make_float4(0.f, 0.f, 0.f, 0.f);
        if (base + r < N) v = ((const float4*)src)[(size_t)(base + r) * 16 + cc];
        xs[cc * 4 + 0][r] = v.x; xs[cc * 4 + 1][r] = v.y;
        xs[cc * 4 + 2][r] = v.z; xs[cc * 4 + 3][r] = v.w;
    }
    __syncthreads();

    int p0 = (tid & 15) * 4, o0 = (tid >> 4) * 4;
    float acc[4][4] = {};
#pragma unroll 8
    for (int c = 0; c < 64; c++) {
        float4 a = *(float4*)&xs[c][p0];
        float4 w = *(float4*)&ws[c][o0];
        acc[0][0] += a.x * w.x; acc[0][1] += a.x * w.y; acc[0][2] += a.x * w.z; acc[0][3] += a.x * w.w;
        acc[1][0] += a.y * w.x; acc[1][1] += a.y * w.y; acc[1][2] += a.y * w.z; acc[1][3] += a.y * w.w;
        acc[2][0] += a.z * w.x; acc[2][1] += a.z * w.y; acc[2][2] += a.z * w.z; acc[2][3] += a.z * w.w;
        acc[3][0] += a.w * w.x; acc[3][1] += a.w * w.y; acc[3][2] += a.w * w.z; acc[3][3] += a.w * w.w;
    }
    float4 bb = ((const float4*)b1)[o0 >> 2];
#pragma unroll
    for (int p = 0; p < 4; p++) {
        int i = base + p0 + p;
        if (i < N) {
            float4 o = make_float4(acc[p][0] + bb.x, acc[p][1] + bb.y,
                                   acc[p][2] + bb.z, acc[p][3] + bb.w);
            ((float4*)dst)[(size_t)i * 16 + (o0 >> 2)] = o;
        }
    }
}

// ---------------------------------------------------------------------------
// Pair-compacted gather-GEMM with VECTOR red accumulation.
// CIN = 64 fixed. Tile: 64 pairs x COUT outputs. grid = (tiles, K)
// Mapping: each thread owns PP pairs x 4 contiguous out-channels -> red.v4.
//   COUT=64: PP=4 (16 pair-groups x 16 chan-groups = 256 thr)
//   COUT=32: PP=2 (32 pair-groups x  8 chan-groups = 256 thr)
// ---------------------------------------------------------------------------
template <int COUT, int PP, bool RELU_SRC>
__global__ void k_pair_gemm(const float* __restrict__ W, const int2* __restrict__ pairsBase,
                            const int* __restrict__ cntArr, const float* __restrict__ src,
                            float* __restrict__ dst) {
    int k = blockIdx.y;
    int n = cntArr[k];
    int t0 = blockIdx.x * 64;
    if (t0 >= n) return;

    __shared__ float xs[64][68];
    __shared__ float ws[64][COUT + 4];
    __shared__ int sdst[64];
    __shared__ int ssrc[64];

    int tid = threadIdx.x;
    const float4* W4 = (const float4*)(W + (size_t)k * 64 * COUT);
    for (int f = tid; f < 64 * COUT / 4; f += 256) {
        int c = f / (COUT / 4), oq = f % (COUT / 4);
        *(float4*)&ws[c][oq * 4] = W4[f];
    }
    if (tid < 64) {
        int2 pr = make_int2(-1, -1);
        if (t0 + tid < n) pr = pairsBase[(size_t)k * NMAX + t0 + tid];
        sdst[tid] = pr.x; ssrc[tid] = pr.y;
    }
    __syncthreads();

    int r = tid & 63, cg = tid >> 6;
    int j = ssrc[r];
#pragma unroll
    for (int m = 0; m < 4; m++) {
        int cc = cg * 4 + m;
        float4 v = make_float4(0.f, 0.f, 0.f, 0.f);
        if (j >= 0) v = ((const float4*)src)[(size_t)j * 16 + cc];
        if (RELU_SRC) {
            v.x = fmaxf(v.x, 0.f); v.y = fmaxf(v.y, 0.f);
            v.z = fmaxf(v.z, 0.f); v.w = fmaxf(v.w, 0.f);
        }
        xs[cc * 4 + 0][r] = v.x; xs[cc * 4 + 1][r] = v.y;
        xs[cc * 4 + 2][r] = v.z; xs[cc * 4 + 3][r] = v.w;
    }
    __syncthreads();

    constexpr int PG = 64 / PP;           // pair-groups
    int pg = tid % PG, og = tid / PG;     // og in [0, COUT/4)
    int p0 = pg * PP, o0 = og * 4;

    float4 acc[PP];
#pragma unroll
    for (int p = 0; p < PP; p++) acc[p] = make_float4(0.f, 0.f, 0.f, 0.f);

#pragma unroll 8
    for (int c = 0; c < 64; c++) {
        float4 w = *(float4*)&ws[c][o0];
        float a[PP];
        if (PP == 4) {
            float4 a4 = *(float4*)&xs[c][p0];
            a[0] = a4.x; a[1] = a4.y; a[2] = a4.z; a[3] = a4.w;
        } else {
            float2 a2 = *(float2*)&xs[c][p0];
            a[0] = a2.x; a[1] = a2.y;
        }
#pragma unroll
        for (int p = 0; p < PP; p++) {
            acc[p].x += a[p] * w.x; acc[p].y += a[p] * w.y;
            acc[p].z += a[p] * w.z; acc[p].w += a[p] * w.w;
        }
    }
#pragma unroll
    for (int p = 0; p < PP; p++) {
        int d = sdst[p0 + p];
        if (d >= 0) red_add_v4(&dst[(size_t)d * COUT + o0], acc[p]);
    }
}

// ---------------------------------------------------------------------------
// Dense-k 27-offset conv for small channels (idx2 lattice, ~42% density).
// ---------------------------------------------------------------------------
template <int CIN, int COUT, int PT, bool RELU, bool RES>
__global__ void k_conv27(const float* __restrict__ feat, const int* __restrict__ idx,
                         const float* __restrict__ W, const float* __restrict__ b,
                         const float* __restrict__ res, float* __restrict__ out,
                         int outStride, int outOff, int N) {
    __shared__ float ws[27 * CIN * COUT];
    __shared__ float sb[COUT];
    int tid = threadIdx.x;
    for (int f = tid; f < 27 * CIN * COUT; f += blockDim.x) ws[f] = W[f];
    if (tid < COUT) sb[tid] = b[tid];
    __syncthreads();

    int i0 = (blockIdx.x * blockDim.x + tid) * PT;

    float acc[PT][COUT];
#pragma unroll
    for (int p = 0; p < PT; p++)
#pragma unroll
        for (int o = 0; o < COUT; o++) acc[p][o] = 0.0f;

    for (int k = 0; k < 27; k++) {
        int jj[PT];
#pragma unroll
        for (int p = 0; p < PT; p++) {
            int i = i0 + p;
            jj[p] = (i < N) ? idx[(size_t)i * 27 + k] : -1;
        }
        const float* wk = &ws[k * CIN * COUT];
#pragma unroll
        for (int c4 = 0; c4 < CIN / 4; c4++) {
            float vv[PT][4];
#pragma unroll
            for (int p = 0; p < PT; p++) {
                float4 v = make_float4(0.f, 0.f, 0.f, 0.f);
                if (jj[p] >= 0) v = ((const float4*)feat)[(size_t)jj[p] * (CIN / 4) + c4];
                vv[p][0] = v.x; vv[p][1] = v.y; vv[p][2] = v.z; vv[p][3] = v.w;
            }
#pragma unroll
            for (int cc = 0; cc < 4; cc++) {
#pragma unroll
                for (int o = 0; o < COUT; o++) {
                    float w = wk[(c4 * 4 + cc) * COUT + o];
#pragma unroll
                    for (int p = 0; p < PT; p++) acc[p][o] += vv[p][cc] * w;
                }
            }
        }
    }

#pragma unroll
    for (int p = 0; p < PT; p++) {
        int i = i0 + p;
        if (i < N) {
            float tmp[COUT];
#pragma unroll
            for (int o = 0; o < COUT; o++) {
                float x = acc[p][o] + sb[o];
                if (RELU) x = fmaxf(x, 0.0f);
                tmp[o] = x;
            }
            float* op = out + (size_t)i * outStride + outOff;
            const float* rp = RES ? (res + (size_t)i * 32 + outOff) : nullptr;
#pragma unroll
            for (int q = 0; q < COUT / 4; q++) {
                float4 t4 = make_float4(tmp[q * 4 + 0], tmp[q * 4 + 1],
                                        tmp[q * 4 + 2], tmp[q * 4 + 3]);
                if (RES) {
                    float4 r4 = ((const float4*)rp)[q];
                    t4.x += r4.x; t4.y += r4.y; t4.z += r4.z; t4.w += r4.w;
                }
                ((float4*)op)[q] = t4;
            }
        }
    }
}

// ---------------------------------------------------------------------------
// Pointwise (kernel-size-1) conv: out = (relu?)(feat @ W + b) (+ res)
// ---------------------------------------------------------------------------
template <int CIN, int COUT, bool RELU, bool RES>
__global__ void k_pw(const float* __restrict__ feat, const float* __restrict__ W,
                     const float* __restrict__ b, const float* __restrict__ res,
                     float* __restrict__ out, int outStride, int outOff, int N) {
    __shared__ float ws[CIN * COUT];
    __shared__ float sb[COUT];
    int tid = threadIdx.x;
    for (int f = tid; f < CIN * COUT; f += blockDim.x) ws[f] = W[f];
    if (tid < COUT) sb[tid] = b[tid];
    __syncthreads();

    int i = blockIdx.x * blockDim.x + tid;
    if (i >= N) return;

    float acc[COUT];
#pragma unroll
    for (int o = 0; o < COUT; o++) acc[o] = sb[o];

#pragma unroll
    for (int c4 = 0; c4 < CIN / 4; c4++) {
        float4 v = ((const float4*)feat)[(size_t)i * (CIN / 4) + c4];
        float vv[4] = {v.x, v.y, v.z, v.w};
#pragma unroll
        for (int cc = 0; cc < 4; cc++)
#pragma unroll
            for (int o = 0; o < COUT; o++)
                acc[o] += vv[cc] * ws[(c4 * 4 + cc) * COUT + o];
    }

    float* op = out + (size_t)i * outStride + outOff;
#pragma unroll
    for (int q = 0; q < COUT / 4; q++) {
        float4 t4 = make_float4(acc[q * 4 + 0], acc[q * 4 + 1], acc[q * 4 + 2], acc[q * 4 + 3]);
        if (RELU) {
            t4.x = fmaxf(t4.x, 0.f); t4.y = fmaxf(t4.y, 0.f);
            t4.z = fmaxf(t4.z, 0.f); t4.w = fmaxf(t4.w, 0.f);
        }
        if (RES) {
            float4 r4 = ((const float4*)(res + (size_t)i * 32 + outOff))[q];
            t4.x += r4.x; t4.y += r4.y; t4.z += r4.z; t4.w += r4.w;
        }
        ((float4*)op)[q] = t4;
    }
}

// ---------------------------------------------------------------------------
// Host launcher
// ---------------------------------------------------------------------------
extern "C" void kernel_launch(void* const* d_in, const int* in_sizes, int n_in,
                              void* d_out, int out_size) {
    const float* x_feat = (const float*)d_in[0];
    const float* f1_ref = (const float*)d_in[1];
    const float* w1     = (const float*)d_in[2];
    const float* b1     = (const float*)d_in[3];
    const float* wd     = (const float*)d_in[4];
    const float* bd     = (const float*)d_in[5];
    const float* rw00   = (const float*)d_in[6];
    const float* rb00   = (const float*)d_in[7];
    const float* rw01   = (const float*)d_in[8];
    const float* rb01   = (const float*)d_in[9];
    const float* rw10   = (const float*)d_in[10];
    const float* rb10   = (const float*)d_in[11];
    const float* rw11   = (const float*)d_in[12];
    const float* rb11   = (const float*)d_in[13];
    const float* rw12   = (const float*)d_in[14];
    const float* rb12   = (const float*)d_in[15];
    const float* w4     = (const float*)d_in[16];
    const float* b4     = (const float*)d_in[17];
    const int*   idx1   = (const int*)d_in[18];
    const int*   idxd   = (const int*)d_in[19];
    const int*   idx2   = (const int*)d_in[20];
    float* outp = (float*)d_out;

    int N  = in_sizes[0] / 64;
    int N2 = in_sizes[19] / 8;

    float *pX, *pF1, *pF2a, *pF2b, *pA8, *pT8;
    int *pCnt1, *pCntd;
    int2 *pPairs1, *pPairsd;
    cudaGetSymbolAddress((void**)&pX, g_X);
    cudaGetSymbolAddress((void**)&pF1, g_F1);
    cudaGetSymbolAddress((void**)&pF2a, g_F2a);
    cudaGetSymbolAddress((void**)&pF2b, g_F2b);
    cudaGetSymbolAddress((void**)&pA8, g_A8);
    cudaGetSymbolAddress((void**)&pT8, g_T8);
    cudaGetSymbolAddress((void**)&pCnt1, g_cnt1);
    cudaGetSymbolAddress((void**)&pCntd, g_cntd);
    cudaGetSymbolAddress((void**)&pPairs1, g_pairs1);
    cudaGetSymbolAddress((void**)&pPairsd, g_pairsd);

    // --- setup: residual add + pair compaction ---
    {
        int n4 = N * 16;
        k_add<<<(n4 + 255) / 256, 256>>>((const float4*)x_feat, (const float4*)f1_ref,
                                         (float4*)pX, n4);
    }
    k_zero_cnt<<<1, 32>>>();
    k_build1<<<(N * 27 + 255) / 256, 256>>>(idx1, N * 27);
    k_buildd<<<(N2 * 8 + 255) / 256, 256>>>(idxd, N2 * 8);

    // --- conv1: center dense + 26 compacted offset GEMMs (red.v4 accumulate) ---
    k_conv1_center<<<(N + 63) / 64, 256>>>(w1, b1, pX, pF1, N);
    {
        dim3 g((N + 63) / 64, 27);
        k_pair_gemm<64, 4, false><<<g, 256>>>(w1, pPairs1, pCnt1, pX, pF1);
    }

    // --- down conv (k2/s2): init with bias, pair GEMMs over relu(F1), then relu ---
    k_bias_init32<<<(N2 * 32 + 255) / 256, 256>>>(pF2a, bd, N2 * 32);
    {
        dim3 g((N2 + 63) / 64, 8);
        k_pair_gemm<32, 2, true><<<g, 256>>>(wd, pPairsd, pCntd, pF1, pF2a);
    }
    k_relu<<<(N2 * 32 + 255) / 256, 256>>>(pF2a, N2 * 32);

    // --- 3 InceptionResNet blocks ---
    float* F  = pF2a;
    float* Fn = pF2b;
    for (int i = 0; i < 3; i++) {
        const float* W00 = rw00 + (size_t)i * 27 * 32 * 8;
        const float* B00 = rb00 + (size_t)i * 8;
        const float* W01 = rw01 + (size_t)i * 27 * 8 * 16;
        const float* B01 = rb01 + (size_t)i * 16;
        const float* W10 = rw10 + (size_t)i * 32 * 8;
        const float* B10 = rb10 + (size_t)i * 8;
        const float* W11 = rw11 + (size_t)i * 27 * 8 * 8;
        const float* B11 = rb11 + (size_t)i * 8;
        const float* W12 = rw12 + (size_t)i * 8 * 16;
        const float* B12 = rb12 + (size_t)i * 16;

        // A8 = relu(conv27(F, rw00))          [32 -> 8]
        k_conv27<32, 8, 4, true, false><<<(N2 + 511) / 512, 128>>>(
            F, idx2, W00, B00, nullptr, pA8, 8, 0, N2);
        // Fn[:, 0:16] = conv27(A8, rw01) + F[:, 0:16]   [8 -> 16]
        k_conv27<8, 16, 2, false, true><<<(N2 + 255) / 256, 128>>>(
            pA8, idx2, W01, B01, F, Fn, 32, 0, N2);
        // T8 = relu(F @ rw10 + b)             [32 -> 8]
        k_pw<32, 8, true, false><<<(N2 + 127) / 128, 128>>>(
            F, W10, B10, nullptr, pT8, 8, 0, N2);
        // A8 = relu(conv27(T8, rw11))         [8 -> 8]
        k_conv27<8, 8, 4, true, false><<<(N2 + 511) / 512, 128>>>(
            pT8, idx2, W11, B11, nullptr, pA8, 8, 0, N2);
        // Fn[:, 16:32] = A8 @ rw12 + b + F[:, 16:32]    [8 -> 16]
        k_pw<8, 16, false, true><<<(N2 + 127) / 128, 128>>>(
            pA8, W12, B12, F, Fn, 32, 16, N2);

        float* t = F; F = Fn; Fn = t;
    }

    // --- enc4: conv27(F, w4) + b4 -> output  [32 -> 8] ---
    k_conv27<32, 8, 4, false, false><<<(N2 + 511) / 512, 128>>>(
        F, idx2, w4, b4, nullptr, outp, 8, 0, N2);
}

// round 3
// speedup vs baseline: 1.1832x; 1.0168x over previous
#include <cuda_runtime.h>

// ---------------------------------------------------------------------------
// Static scratch (sanctioned workaround for no-alloc rule)
// ---------------------------------------------------------------------------
#define NMAX 250112  // >= 250000, multiple of 64

__device__ __align__(256) float g_X  [(size_t)NMAX * 64];
__device__ __align__(256) float g_F1 [(size_t)NMAX * 64];
__device__ __align__(256) float g_F2a[(size_t)NMAX * 32];
__device__ __align__(256) float g_F2b[(size_t)NMAX * 32];
__device__ __align__(256) float g_A8 [(size_t)NMAX * 8];
__device__ __align__(256) float g_T8 [(size_t)NMAX * 8];
__device__ int  g_cnt1[27];
__device__ int  g_cntd[8];
__device__ __align__(256) int2 g_pairs1[(size_t)27 * NMAX];
__device__ __align__(256) int2 g_pairsd[(size_t)8  * NMAX];

typedef unsigned long long u64;

// ---------------------------------------------------------------------------
// Packed f32x2 helpers (SASS FFMA2 — only reachable via PTX fma.rn.f32x2)
// ---------------------------------------------------------------------------
__device__ __forceinline__ u64 pack2(float a, float b) {
    u64 r;
    asm("mov.b64 %0, {%1, %2};" : "=l"(r) : "f"(a), "f"(b));
    return r;
}
__device__ __forceinline__ void unpack2(u64 v, float& a, float& b) {
    asm("mov.b64 {%0, %1}, %2;" : "=f"(a), "=f"(b) : "l"(v));
}
__device__ __forceinline__ u64 fma2(u64 a, u64 b, u64 c) {
    u64 d;
    asm("fma.rn.f32x2 %0, %1, %2, %3;" : "=l"(d) : "l"(a), "l"(b), "l"(c));
    return d;
}

// ---------------------------------------------------------------------------
// Vector reduction helper (sm_90+): one LTS request for 4 channels
// ---------------------------------------------------------------------------
__device__ __forceinline__ void red_add_v4(float* p, float4 v) {
    asm volatile("red.global.add.v4.f32 [%0], {%1, %2, %3, %4};"
                 :: "l"(p), "f"(v.x), "f"(v.y), "f"(v.z), "f"(v.w)
                 : "memory");
}

// ---------------------------------------------------------------------------
// Elementwise helpers
// ---------------------------------------------------------------------------
__global__ void k_add(const float4* __restrict__ a, const float4* __restrict__ b,
                      float4* __restrict__ o, int n4) {
    int t = blockIdx.x * blockDim.x + threadIdx.x;
    if (t < n4) {
        float4 x = a[t], y = b[t];
        o[t] = make_float4(x.x + y.x, x.y + y.y, x.z + y.z, x.w + y.w);
    }
}

__global__ void k_bias_init32(float* __restrict__ buf, const float* __restrict__ b, int n) {
    int t = blockIdx.x * blockDim.x + threadIdx.x;
    if (t < n) buf[t] = b[t & 31];
}

__global__ void k_relu(float* __restrict__ buf, int n) {
    int t = blockIdx.x * blockDim.x + threadIdx.x;
    if (t < n) buf[t] = fmaxf(buf[t], 0.0f);
}

// ---------------------------------------------------------------------------
// Pair-list construction with BLOCK-AGGREGATED atomics.
// ---------------------------------------------------------------------------
__global__ void k_zero_cnt() {
    int t = threadIdx.x;
    if (t < 27) g_cnt1[t] = 0;
    if (t < 8)  g_cntd[t] = 0;
}

__global__ void k_build1(const int* __restrict__ idx, int total) {  // total = N*27
    __shared__ int scnt[27];
    __shared__ int sbase[27];
    int tid = threadIdx.x;
    if (tid < 27) scnt[tid] = 0;
    __syncthreads();

    int t = blockIdx.x * blockDim.x + tid;
    int k = -1, i = 0, j = 0, rank = 0;
    if (t < total) {
        int kk = t % 27;
        if (kk != 13) {                 // center offset handled densely
            int jj = idx[t];
            if (jj >= 0) {
                k = kk; j = jj; i = t / 27;
                rank = atomicAdd(&scnt[k], 1);
            }
        }
    }
    __syncthreads();
    if (tid < 27 && scnt[tid] > 0)
        sbase[tid] = atomicAdd(&g_cnt1[tid], scnt[tid]);
    __syncthreads();
    if (k >= 0)
        g_pairs1[(size_t)k * NMAX + sbase[k] + rank] = make_int2(i, j);
}

__global__ void k_buildd(const int* __restrict__ idx, int total) {  // total = N2*8
    __shared__ int scnt[8];
    __shared__ int sbase[8];
    int tid = threadIdx.x;
    if (tid < 8) scnt[tid] = 0;
    __syncthreads();

    int t = blockIdx.x * blockDim.x + tid;
    int k = -1, i = 0, j = 0, rank = 0;
    if (t < total) {
        int jj = idx[t];
        if (jj >= 0) {
            k = t % 8; j = jj; i = t / 8;
            rank = atomicAdd(&scnt[k], 1);
        }
    }
    __syncthreads();
    if (tid < 8 && scnt[tid] > 0)
        sbase[tid] = atomicAdd(&g_cntd[tid], scnt[tid]);
    __syncthreads();
    if (k >= 0)
        g_pairsd[(size_t)k * NMAX + sbase[k] + rank] = make_int2(i, j);
}

// ---------------------------------------------------------------------------
// conv1 center offset (k==13, identity map): F1 = X @ W13 + b1  (dense GEMM)
// ---------------------------------------------------------------------------
__global__ void k_conv1_center(const float* __restrict__ W, const float* __restrict__ b1,
                               const float* __restrict__ src, float* __restrict__ dst, int N) {
    __shared__ __align__(16) float xs[64][68];
    __shared__ __align__(16) float ws[64][68];
    int tid = threadIdx.x;
    int base = blockIdx.x * 64;

    const float4* W4 = (const float4*)(W + 13 * 4096);
    for (int f = tid; f < 1024; f += 256) {
        int c = f >> 4, oq = f & 15;
        *(float4*)&ws[c][oq * 4] = W4[f];
    }
    int r = tid & 63, cg = tid >> 6;
#pragma unroll
    for (int m = 0; m < 4; m++) {
        int cc = cg * 4 + m;
        float4 v = make_float4(0.f, 0.f, 0.f, 0.f);
        if (base + r < N) v = ((const float4*)src)[(size_t)(base + r) * 16 + cc];
        xs[cc * 4 + 0][r] = v.x; xs[cc * 4 + 1][r] = v.y;
        xs[cc * 4 + 2][r] = v.z; xs[cc * 4 + 3][r] = v.w;
    }
    __syncthreads();

    int p0 = (tid & 15) * 4, o0 = (tid >> 4) * 4;
    u64 acc2[4][2] = {};
#pragma unroll 8
    for (int c = 0; c < 64; c++) {
        float4 a = *(float4*)&xs[c][p0];
        u64 w01 = *(const u64*)&ws[c][o0];
        u64 w23 = *(const u64*)&ws[c][o0 + 2];
        float ap[4] = {a.x, a.y, a.z, a.w};
#pragma unroll
        for (int p = 0; p < 4; p++) {
            u64 ad = pack2(ap[p], ap[p]);
            acc2[p][0] = fma2(ad, w01, acc2[p][0]);
            acc2[p][1] = fma2(ad, w23, acc2[p][1]);
        }
    }
    float4 bb = ((const float4*)b1)[o0 >> 2];
#pragma unroll
    for (int p = 0; p < 4; p++) {
        int i = base + p0 + p;
        if (i < N) {
            float a0, a1, a2, a3;
            unpack2(acc2[p][0], a0, a1);
            unpack2(acc2[p][1], a2, a3);
            float4 o = make_float4(a0 + bb.x, a1 + bb.y, a2 + bb.z, a3 + bb.w);
            ((float4*)dst)[(size_t)i * 16 + (o0 >> 2)] = o;
        }
    }
}

// ---------------------------------------------------------------------------
// Pair-compacted gather-GEMM with VECTOR red accumulation + FFMA2.
// ---------------------------------------------------------------------------
template <int COUT, int PP, bool RELU_SRC>
__global__ void k_pair_gemm(const float* __restrict__ W, const int2* __restrict__ pairsBase,
                            const int* __restrict__ cntArr, const float* __restrict__ src,
                            float* __restrict__ dst) {
    int k = blockIdx.y;
    int n = cntArr[k];
    int t0 = blockIdx.x * 64;
    if (t0 >= n) return;

    __shared__ __align__(16) float xs[64][68];
    __shared__ __align__(16) float ws[64][COUT + 4];
    __shared__ int sdst[64];
    __shared__ int ssrc[64];

    int tid = threadIdx.x;
    const float4* W4 = (const float4*)(W + (size_t)k * 64 * COUT);
    for (int f = tid; f < 64 * COUT / 4; f += 256) {
        int c = f / (COUT / 4), oq = f % (COUT / 4);
        *(float4*)&ws[c][oq * 4] = W4[f];
    }
    if (tid < 64) {
        int2 pr = make_int2(-1, -1);
        if (t0 + tid < n) pr = pairsBase[(size_t)k * NMAX + t0 + tid];
        sdst[tid] = pr.x; ssrc[tid] = pr.y;
    }
    __syncthreads();

    int r = tid & 63, cg = tid >> 6;
    int j = ssrc[r];
#pragma unroll
    for (int m = 0; m < 4; m++) {
        int cc = cg * 4 + m;
        float4 v = make_float4(0.f, 0.f, 0.f, 0.f);
        if (j >= 0) v = ((const float4*)src)[(size_t)j * 16 + cc];
        if (RELU_SRC) {
            v.x = fmaxf(v.x, 0.f); v.y = fmaxf(v.y, 0.f);
            v.z = fmaxf(v.z, 0.f); v.w = fmaxf(v.w, 0.f);
        }
        xs[cc * 4 + 0][r] = v.x; xs[cc * 4 + 1][r] = v.y;
        xs[cc * 4 + 2][r] = v.z; xs[cc * 4 + 3][r] = v.w;
    }
    __syncthreads();

    constexpr int PG = 64 / PP;           // pair-groups
    int pg = tid % PG, og = tid / PG;     // og in [0, COUT/4)
    int p0 = pg * PP, o0 = og * 4;

    u64 acc2[PP][2] = {};
#pragma unroll 8
    for (int c = 0; c < 64; c++) {
        u64 w01 = *(const u64*)&ws[c][o0];
        u64 w23 = *(const u64*)&ws[c][o0 + 2];
        float a[PP];
        if (PP == 4) {
            float4 a4 = *(float4*)&xs[c][p0];
            a[0] = a4.x; a[1] = a4.y; a[2] = a4.z; a[3] = a4.w;
        } else {
            float2 a2 = *(float2*)&xs[c][p0];
            a[0] = a2.x; a[1] = a2.y;
        }
#pragma unroll
        for (int p = 0; p < PP; p++) {
            u64 ad = pack2(a[p], a[p]);
            acc2[p][0] = fma2(ad, w01, acc2[p][0]);
            acc2[p][1] = fma2(ad, w23, acc2[p][1]);
        }
    }
#pragma unroll
    for (int p = 0; p < PP; p++) {
        int d = sdst[p0 + p];
        if (d >= 0) {
            float4 v;
            unpack2(acc2[p][0], v.x, v.y);
            unpack2(acc2[p][1], v.z, v.w);
            red_add_v4(&dst[(size_t)d * COUT + o0], v);
        }
    }
}

// ---------------------------------------------------------------------------
// Dense-k 27-offset conv with FFMA2 inner product (idx2 lattice, ~40% density).
// ---------------------------------------------------------------------------
template <int CIN, int COUT, int PT, bool RELU, bool RES>
__global__ void k_conv27(const float* __restrict__ feat, const int* __restrict__ idx,
                         const float* __restrict__ W, const float* __restrict__ b,
                         const float* __restrict__ res, float* __restrict__ out,
                         int outStride, int outOff, int N) {
    __shared__ __align__(16) float ws[27 * CIN * COUT];
    __shared__ float sb[COUT];
    int tid = threadIdx.x;
    for (int f = tid; f < 27 * CIN * COUT; f += blockDim.x) ws[f] = W[f];
    if (tid < COUT) sb[tid] = b[tid];
    __syncthreads();

    int i0 = (blockIdx.x * blockDim.x + tid) * PT;

    u64 acc[PT][COUT / 2] = {};

    for (int k = 0; k < 27; k++) {
        int jj[PT];
#pragma unroll
        for (int p = 0; p < PT; p++) {
            int i = i0 + p;
            jj[p] = (i < N) ? idx[(size_t)i * 27 + k] : -1;
        }
        const float* wk = &ws[k * CIN * COUT];
#pragma unroll
        for (int c4 = 0; c4 < CIN / 4; c4++) {
            float vv[PT][4];
#pragma unroll
            for (int p = 0; p < PT; p++) {
                float4 v = make_float4(0.f, 0.f, 0.f, 0.f);
                if (jj[p] >= 0) v = ((const float4*)feat)[(size_t)jj[p] * (CIN / 4) + c4];
                vv[p][0] = v.x; vv[p][1] = v.y; vv[p][2] = v.z; vv[p][3] = v.w;
            }
#pragma unroll
            for (int cc = 0; cc < 4; cc++) {
                const u64* w2 = (const u64*)&wk[(c4 * 4 + cc) * COUT];
                u64 wq[COUT / 2];
#pragma unroll
                for (int q = 0; q < COUT / 2; q++) wq[q] = w2[q];
#pragma unroll
                for (int p = 0; p < PT; p++) {
                    u64 ad = pack2(vv[p][cc], vv[p][cc]);
#pragma unroll
                    for (int q = 0; q < COUT / 2; q++)
                        acc[p][q] = fma2(ad, wq[q], acc[p][q]);
                }
            }
        }
    }

#pragma unroll
    for (int p = 0; p < PT; p++) {
        int i = i0 + p;
        if (i < N) {
            float tmp[COUT];
#pragma unroll
            for (int q = 0; q < COUT / 2; q++)
                unpack2(acc[p][q], tmp[2 * q], tmp[2 * q + 1]);
#pragma unroll
            for (int o = 0; o < COUT; o++) {
                float x = tmp[o] + sb[o];
                if (RELU) x = fmaxf(x, 0.0f);
                tmp[o] = x;
            }
            float* op = out + (size_t)i * outStride + outOff;
            const float* rp = RES ? (res + (size_t)i * 32 + outOff) : nullptr;
#pragma unroll
            for (int q = 0; q < COUT / 4; q++) {
                float4 t4 = make_float4(tmp[q * 4 + 0], tmp[q * 4 + 1],
                                        tmp[q * 4 + 2], tmp[q * 4 + 3]);
                if (RES) {
                    float4 r4 = ((const float4*)rp)[q];
                    t4.x += r4.x; t4.y += r4.y; t4.z += r4.z; t4.w += r4.w;
                }
                ((float4*)op)[q] = t4;
            }
        }
    }
}

// ---------------------------------------------------------------------------
// Pointwise (kernel-size-1) conv: out = (relu?)(feat @ W + b) (+ res)
// ---------------------------------------------------------------------------
template <int CIN, int COUT, bool RELU, bool RES>
__global__ void k_pw(const float* __restrict__ feat, const float* __restrict__ W,
                     const float* __restrict__ b, const float* __restrict__ res,
                     float* __restrict__ out, int outStride, int outOff, int N) {
    __shared__ __align__(16) float ws[CIN * COUT];
    __shared__ float sb[COUT];
    int tid = threadIdx.x;
    for (int f = tid; f < CIN * COUT; f += blockDim.x) ws[f] = W[f];
    if (tid < COUT) sb[tid] = b[tid];
    __syncthreads();

    int i = blockIdx.x * blockDim.x + tid;
    if (i >= N) return;

    u64 acc[COUT / 2] = {};

#pragma unroll
    for (int c4 = 0; c4 < CIN / 4; c4++) {
        float4 v = ((const float4*)feat)[(size_t)i * (CIN / 4) + c4];
        float vv[4] = {v.x, v.y, v.z, v.w};
#pragma unroll
        for (int cc = 0; cc < 4; cc++) {
            const u64* w2 = (const u64*)&ws[(c4 * 4 + cc) * COUT];
            u64 ad = pack2(vv[cc], vv[cc]);
#pragma unroll
            for (int q = 0; q < COUT / 2; q++)
                acc[q] = fma2(ad, w2[q], acc[q]);
        }
    }

    float tmp[COUT];
#pragma unroll
    for (int q = 0; q < COUT / 2; q++)
        unpack2(acc[q], tmp[2 * q], tmp[2 * q + 1]);

    float* op = out + (size_t)i * outStride + outOff;
#pragma unroll
    for (int q = 0; q < COUT / 4; q++) {
        float4 t4 = make_float4(tmp[q * 4 + 0] + sb[q * 4 + 0], tmp[q * 4 + 1] + sb[q * 4 + 1],
                                tmp[q * 4 + 2] + sb[q * 4 + 2], tmp[q * 4 + 3] + sb[q * 4 + 3]);
        if (RELU) {
            t4.x = fmaxf(t4.x, 0.f); t4.y = fmaxf(t4.y, 0.f);
            t4.z = fmaxf(t4.z, 0.f); t4.w = fmaxf(t4.w, 0.f);
        }
        if (RES) {
            float4 r4 = ((const float4*)(res + (size_t)i * 32 + outOff))[q];
            t4.x += r4.x; t4.y += r4.y; t4.z += r4.z; t4.w += r4.w;
        }
        ((float4*)op)[q] = t4;
    }
}

// ---------------------------------------------------------------------------
// Host launcher
// ---------------------------------------------------------------------------
extern "C" void kernel_launch(void* const* d_in, const int* in_sizes, int n_in,
                              void* d_out, int out_size) {
    const float* x_feat = (const float*)d_in[0];
    const float* f1_ref = (const float*)d_in[1];
    const float* w1     = (const float*)d_in[2];
    const float* b1     = (const float*)d_in[3];
    const float* wd     = (const float*)d_in[4];
    const float* bd     = (const float*)d_in[5];
    const float* rw00   = (const float*)d_in[6];
    const float* rb00   = (const float*)d_in[7];
    const float* rw01   = (const float*)d_in[8];
    const float* rb01   = (const float*)d_in[9];
    const float* rw10   = (const float*)d_in[10];
    const float* rb10   = (const float*)d_in[11];
    const float* rw11   = (const float*)d_in[12];
    const float* rb11   = (const float*)d_in[13];
    const float* rw12   = (const float*)d_in[14];
    const float* rb12   = (const float*)d_in[15];
    const float* w4     = (const float*)d_in[16];
    const float* b4     = (const float*)d_in[17];
    const int*   idx1   = (const int*)d_in[18];
    const int*   idxd   = (const int*)d_in[19];
    const int*   idx2   = (const int*)d_in[20];
    float* outp = (float*)d_out;

    int N  = in_sizes[0] / 64;
    int N2 = in_sizes[19] / 8;

    float *pX, *pF1, *pF2a, *pF2b, *pA8, *pT8;
    int *pCnt1, *pCntd;
    int2 *pPairs1, *pPairsd;
    cudaGetSymbolAddress((void**)&pX, g_X);
    cudaGetSymbolAddress((void**)&pF1, g_F1);
    cudaGetSymbolAddress((void**)&pF2a, g_F2a);
    cudaGetSymbolAddress((void**)&pF2b, g_F2b);
    cudaGetSymbolAddress((void**)&pA8, g_A8);
    cudaGetSymbolAddress((void**)&pT8, g_T8);
    cudaGetSymbolAddress((void**)&pCnt1, g_cnt1);
    cudaGetSymbolAddress((void**)&pCntd, g_cntd);
    cudaGetSymbolAddress((void**)&pPairs1, g_pairs1);
    cudaGetSymbolAddress((void**)&pPairsd, g_pairsd);

    // --- setup: residual add + pair compaction ---
    {
        int n4 = N * 16;
        k_add<<<(n4 + 255) / 256, 256>>>((const float4*)x_feat, (const float4*)f1_ref,
                                         (float4*)pX, n4);
    }
    k_zero_cnt<<<1, 32>>>();
    k_build1<<<(N * 27 + 255) / 256, 256>>>(idx1, N * 27);
    k_buildd<<<(N2 * 8 + 255) / 256, 256>>>(idxd, N2 * 8);

    // --- conv1: center dense + 26 compacted offset GEMMs (red.v4 accumulate) ---
    k_conv1_center<<<(N + 63) / 64, 256>>>(w1, b1, pX, pF1, N);
    {
        dim3 g((N + 63) / 64, 27);
        k_pair_gemm<64, 4, false><<<g, 256>>>(w1, pPairs1, pCnt1, pX, pF1);
    }

    // --- down conv (k2/s2): init with bias, pair GEMMs over relu(F1), then relu ---
    k_bias_init32<<<(N2 * 32 + 255) / 256, 256>>>(pF2a, bd, N2 * 32);
    {
        dim3 g((N2 + 63) / 64, 8);
        k_pair_gemm<32, 2, true><<<g, 256>>>(wd, pPairsd, pCntd, pF1, pF2a);
    }
    k_relu<<<(N2 * 32 + 255) / 256, 256>>>(pF2a, N2 * 32);

    // --- 3 InceptionResNet blocks ---
    float* F  = pF2a;
    float* Fn = pF2b;
    for (int i = 0; i < 3; i++) {
        const float* W00 = rw00 + (size_t)i * 27 * 32 * 8;
        const float* B00 = rb00 + (size_t)i * 8;
        const float* W01 = rw01 + (size_t)i * 27 * 8 * 16;
        const float* B01 = rb01 + (size_t)i * 16;
        const float* W10 = rw10 + (size_t)i * 32 * 8;
        const float* B10 = rb10 + (size_t)i * 8;
        const float* W11 = rw11 + (size_t)i * 27 * 8 * 8;
        const float* B11 = rb11 + (size_t)i * 8;
        const float* W12 = rw12 + (size_t)i * 8 * 16;
        const float* B12 = rb12 + (size_t)i * 16;

        // A8 = relu(conv27(F, rw00))          [32 -> 8]
        k_conv27<32, 8, 4, true, false><<<(N2 + 511) / 512, 128>>>(
            F, idx2, W00, B00, nullptr, pA8, 8, 0, N2);
        // Fn[:, 0:16] = conv27(A8, rw01) + F[:, 0:16]   [8 -> 16]
        k_conv27<8, 16, 2, false, true><<<(N2 + 255) / 256, 128>>>(
            pA8, idx2, W01, B01, F, Fn, 32, 0, N2);
        // T8 = relu(F @ rw10 + b)             [32 -> 8]
        k_pw<32, 8, true, false><<<(N2 + 127) / 128, 128>>>(
            F, W10, B10, nullptr, pT8, 8, 0, N2);
        // A8 = relu(conv27(T8, rw11))         [8 -> 8]
        k_conv27<8, 8, 4, true, false><<<(N2 + 511) / 512, 128>>>(
            pT8, idx2, W11, B11, nullptr, pA8, 8, 0, N2);
        // Fn[:, 16:32] = A8 @ rw12 + b + F[:, 16:32]    [8 -> 16]
        k_pw<8, 16, false, true><<<(N2 + 127) / 128, 128>>>(
            pA8, W12, B12, F, Fn, 32, 16, N2);

        float* t = F; F = Fn; Fn = t;
    }

    // --- enc4: conv27(F, w4) + b4 -> output  [32 -> 8] ---
    k_conv27<32, 8, 4, false, false><<<(N2 + 511) / 512, 128>>>(
        F, idx2, w4, b4, nullptr, outp, 8, 0, N2);
}